// round 4
// baseline (speedup 1.0000x reference)
#include <cuda_runtime.h>

#define DDIM 128
#define KCB  1024
#define MT   128          // rows per CTA
#define NT   64           // codes per chunk
#define TH   256
#define NCHUNK (KCB / NT) // 16

__device__ float g_enorm[KCB];

static __device__ __forceinline__ unsigned long long pk2(float lo, float hi) {
    unsigned long long r;
    asm("mov.b64 %0, {%1, %2};" : "=l"(r) : "f"(lo), "f"(hi));
    return r;
}
static __device__ __forceinline__ void fma2(unsigned long long& d,
                                            unsigned long long a,
                                            unsigned long long b) {
    asm("fma.rn.f32x2 %0, %1, %2, %3;" : "=l"(d) : "l"(a), "l"(b), "l"(d));
}
static __device__ __forceinline__ float2 upk2(unsigned long long v) {
    float2 f;
    asm("mov.b64 {%0, %1}, %2;" : "=f"(f.x), "=f"(f.y) : "l"(v));
    return f;
}

__global__ void enorm_kernel(const float* __restrict__ embed) {
    int k = blockIdx.x * blockDim.x + threadIdx.x;
    if (k < KCB) {
        const float4* row = reinterpret_cast<const float4*>(embed + (long long)k * DDIM);
        float s = 0.f;
        #pragma unroll
        for (int i = 0; i < DDIM / 4; i++) {
            float4 v = row[i];
            s = fmaf(v.x, v.x, s);
            s = fmaf(v.y, v.y, s);
            s = fmaf(v.z, v.z, s);
            s = fmaf(v.w, v.w, s);
        }
        g_enorm[k] = s;
    }
}

__global__ __launch_bounds__(TH, 2)
void vq_kernel(const float* __restrict__ x, const float* __restrict__ embed,
               float* __restrict__ out, int nrows, int write_idx) {
    extern __shared__ float sm[];
    float* xs = sm;                 // [DDIM][MT]  (d-major)  64 KB
    float* es = sm + DDIM * MT;     // [DDIM][NT]  (d-major)  32 KB

    const int tid = threadIdx.x;
    const int tx = tid & 15;        // 16 lanes over N
    const int ty = tid >> 4;        // 16 lanes over M
    const int rowBase = blockIdx.x * MT;

    // ---- load x tile transposed into smem (once per CTA) ----
    {
        int m = tid & 127;
        int half = tid >> 7;
        const float4* gx = reinterpret_cast<const float4*>(
            x + (long long)(rowBase + m) * DDIM);
        #pragma unroll
        for (int j = 0; j < 16; j++) {
            int d4 = half + 2 * j;
            float4 v = gx[d4];
            xs[(d4 * 4 + 0) * MT + m] = v.x;
            xs[(d4 * 4 + 1) * MT + m] = v.y;
            xs[(d4 * 4 + 2) * MT + m] = v.z;
            xs[(d4 * 4 + 3) * MT + m] = v.w;
        }
    }

    float best[8];
    int   bidx[8];
    #pragma unroll
    for (int i = 0; i < 8; i++) { best[i] = -3.4e38f; bidx[i] = 0; }

    for (int c = 0; c < NCHUNK; c++) {
        const int kbase = c * NT;
        // ---- load embed chunk transposed ----
        {
            int n = tid & 63;
            int q = tid >> 6;       // 0..3
            const float4* ge = reinterpret_cast<const float4*>(
                embed + (long long)(kbase + n) * DDIM);
            #pragma unroll
            for (int j = 0; j < 8; j++) {
                int d4 = q + 4 * j;
                float4 v = ge[d4];
                es[(d4 * 4 + 0) * NT + n] = v.x;
                es[(d4 * 4 + 1) * NT + n] = v.y;
                es[(d4 * 4 + 2) * NT + n] = v.z;
                es[(d4 * 4 + 3) * NT + n] = v.w;
            }
        }
        __syncthreads();

        unsigned long long acc[8][2];
        #pragma unroll
        for (int i = 0; i < 8; i++) { acc[i][0] = 0ull; acc[i][1] = 0ull; }

        // ---- mainloop: 8x4 micro-tile via packed f32x2 FMAs ----
        #pragma unroll 4
        for (int d = 0; d < DDIM; d++) {
            float4 a0 = *reinterpret_cast<const float4*>(&xs[d * MT + ty * 8]);
            float4 a1 = *reinterpret_cast<const float4*>(&xs[d * MT + ty * 8 + 4]);
            float4 b  = *reinterpret_cast<const float4*>(&es[d * NT + tx * 4]);
            unsigned long long b01 = pk2(b.x, b.y);
            unsigned long long b23 = pk2(b.z, b.w);
            float am[8] = {a0.x, a0.y, a0.z, a0.w, a1.x, a1.y, a1.z, a1.w};
            #pragma unroll
            for (int i = 0; i < 8; i++) {
                unsigned long long ai = pk2(am[i], am[i]);
                fma2(acc[i][0], ai, b01);
                fma2(acc[i][1], ai, b23);
            }
        }
        __syncthreads();   // protect es before next chunk overwrites it

        // ---- per-chunk argmax update: score = 2*dot - ||e||^2 ----
        const int k0 = kbase + tx * 4;
        float en0 = g_enorm[k0 + 0];
        float en1 = g_enorm[k0 + 1];
        float en2 = g_enorm[k0 + 2];
        float en3 = g_enorm[k0 + 3];
        #pragma unroll
        for (int i = 0; i < 8; i++) {
            float2 p0 = upk2(acc[i][0]);
            float2 p1 = upk2(acc[i][1]);
            float s0 = 2.f * p0.x - en0;
            float s1 = 2.f * p0.y - en1;
            float s2 = 2.f * p1.x - en2;
            float s3 = 2.f * p1.y - en3;
            if (s0 > best[i]) { best[i] = s0; bidx[i] = k0 + 0; }
            if (s1 > best[i]) { best[i] = s1; bidx[i] = k0 + 1; }
            if (s2 > best[i]) { best[i] = s2; bidx[i] = k0 + 2; }
            if (s3 > best[i]) { best[i] = s3; bidx[i] = k0 + 3; }
        }
    }

    // ---- cross-tx reduction in smem (reuse es region) ----
    float* rv = es;                       // [MT][16] floats  (8 KB)
    int*   ri = (int*)(es + MT * 16);     // [MT][16] ints    (8 KB)
    int*   bi = (int*)(es + MT * 32);     // [MT] winning idx
    #pragma unroll
    for (int i = 0; i < 8; i++) {
        int m = ty * 8 + i;
        rv[m * 16 + tx] = best[i];
        ri[m * 16 + tx] = bidx[i];
    }
    __syncthreads();
    if (tid < MT) {
        int m = tid;
        float bv = rv[m * 16];
        int   bk = ri[m * 16];
        #pragma unroll
        for (int t = 1; t < 16; t++) {
            float v = rv[m * 16 + t];
            int   k = ri[m * 16 + t];
            if (v > bv || (v == bv && k < bk)) { bv = v; bk = k; }
        }
        bi[m] = bk;
        if (write_idx)
            out[(long long)nrows * DDIM + rowBase + m] = (float)bk;
    }
    __syncthreads();

    // ---- gather winning codewords: coalesced float4 copy ----
    {
        float4* go = reinterpret_cast<float4*>(out);
        const float4* ge = reinterpret_cast<const float4*>(embed);
        #pragma unroll
        for (int i = 0; i < 16; i++) {
            int idx = tid + i * TH;       // 0..4095 over [128 rows][32 f4]
            int row = idx >> 5;
            int c4  = idx & 31;
            int k = bi[row];
            go[((long long)(rowBase + row) << 5) + c4] = ge[(k << 5) + c4];
        }
    }
}

extern "C" void kernel_launch(void* const* d_in, const int* in_sizes, int n_in,
                              void* d_out, int out_size) {
    const float* x     = (const float*)d_in[0];
    const float* embed = (const float*)d_in[1];
    float* out = (float*)d_out;

    int nrows = in_sizes[0] / DDIM;                        // 96000
    int write_idx = (out_size >= nrows * DDIM + nrows) ? 1 : 0;

    enorm_kernel<<<(KCB + 255) / 256, 256>>>(embed);

    cudaFuncSetAttribute(vq_kernel,
                         cudaFuncAttributeMaxDynamicSharedMemorySize, 98304);
    vq_kernel<<<nrows / MT, TH, 98304>>>(x, embed, out, nrows, write_idx);
}

// round 7
// speedup vs baseline: 1.6394x; 1.6394x over previous
#include <cuda_runtime.h>
#include <cuda_bf16.h>
#include <cstdint>

#define DDIM 128
#define KCB  1024
#define MT   128          // rows per CTA
#define NC   64           // codes per chunk
#define NCHUNK 16
#define TH   256

#define ASTRIDE 272                   // bytes per smem row (136 bf16, pad for LDSM)
#define AMAT   (128 * ASTRIDE)        // 34816 B per A term matrix
#define BMAT   (64 * ASTRIDE)         // 17408 B per B term matrix
#define A_OFF  0                      // A: h,m,l consecutive (3*AMAT)
#define B_OFF  (3 * AMAT)             // 104448; 2 stages x 3 terms
#define EN_OFF (B_OFF + 2 * 3 * BMAT) // 208896: 1024 floats
#define RED_OFF (EN_OFF + 4096)       // 212992: val f32[256] + idx i32[256]
#define SMEM_TOTAL (RED_OFF + 2048)   // 215040

__device__ float g_enorm[KCB];
__device__ __align__(16) unsigned short g_bsplit[3][KCB][DDIM];  // bf16 bits: h,m,l

// ---------------- PTX helpers (baseline ISA only) ----------------
static __device__ __forceinline__ uint32_t smem_u32(const void* p) {
    uint32_t a;
    asm("{ .reg .u64 t; cvta.to.shared.u64 t, %1; cvt.u32.u64 %0, t; }"
        : "=r"(a) : "l"(p));
    return a;
}
static __device__ __forceinline__ void ldsm4(uint32_t* r, uint32_t a) {
    asm volatile("ldmatrix.sync.aligned.m8n8.x4.shared.b16 {%0,%1,%2,%3}, [%4];"
                 : "=r"(r[0]), "=r"(r[1]), "=r"(r[2]), "=r"(r[3]) : "r"(a));
}
static __device__ __forceinline__ void mma16816(float* c, const uint32_t* a,
                                                const uint32_t* b2) {
    asm volatile(
        "mma.sync.aligned.m16n8k16.row.col.f32.bf16.bf16.f32 "
        "{%0,%1,%2,%3}, {%4,%5,%6,%7}, {%8,%9}, {%0,%1,%2,%3};"
        : "+f"(c[0]), "+f"(c[1]), "+f"(c[2]), "+f"(c[3])
        : "r"(a[0]), "r"(a[1]), "r"(a[2]), "r"(a[3]), "r"(b2[0]), "r"(b2[1]));
}
static __device__ __forceinline__ void cpasync16(uint32_t dst, const void* src) {
    asm volatile("cp.async.cg.shared.global [%0], [%1], 16;" :: "r"(dst), "l"(src));
}
static __device__ __forceinline__ void cp_commit() {
    asm volatile("cp.async.commit_group;" ::: "memory");
}
static __device__ __forceinline__ void cp_wait1() {
    asm volatile("cp.async.wait_group 1;" ::: "memory");
}
static __device__ __forceinline__ void cp_wait0() {
    asm volatile("cp.async.wait_group 0;" ::: "memory");
}
static __device__ __forceinline__ unsigned short bfbits(__nv_bfloat16 h) {
    return *reinterpret_cast<unsigned short*>(&h);
}

// ---------------- prep kernels ----------------
__global__ void prep_split_kernel(const float* __restrict__ embed) {
    int i = blockIdx.x * blockDim.x + threadIdx.x;
    if (i < KCB * DDIM) {
        float v = embed[i];
        __nv_bfloat16 h = __float2bfloat16_rn(v);
        float r = v - __bfloat162float(h);
        __nv_bfloat16 m = __float2bfloat16_rn(r);
        r -= __bfloat162float(m);
        __nv_bfloat16 lo = __float2bfloat16_rn(r);
        unsigned short* p = &g_bsplit[0][0][0];
        p[i] = bfbits(h);
        p[KCB * DDIM + i] = bfbits(m);
        p[2 * KCB * DDIM + i] = bfbits(lo);
    }
}
__global__ void enorm_kernel(const float* __restrict__ embed) {
    int k = blockIdx.x * blockDim.x + threadIdx.x;
    if (k < KCB) {
        const float4* row = reinterpret_cast<const float4*>(embed + (long long)k * DDIM);
        float s = 0.f;
        #pragma unroll
        for (int i = 0; i < DDIM / 4; i++) {
            float4 v = row[i];
            s = fmaf(v.x, v.x, s); s = fmaf(v.y, v.y, s);
            s = fmaf(v.z, v.z, s); s = fmaf(v.w, v.w, s);
        }
        g_enorm[k] = s;
    }
}

// ---------------- B chunk loader (cp.async, padded rows) ----------------
static __device__ __forceinline__ void load_b(uint32_t sb, int c, int s, int tid) {
    uint32_t dbase = sb + B_OFF + (uint32_t)s * (3 * BMAT);
    const char* gb = reinterpret_cast<const char*>(&g_bsplit[0][0][0]);
    #pragma unroll
    for (int i = 0; i < 12; i++) {
        int e = tid + i * TH;         // 0..3071  (3 terms x 64 rows x 16 segs)
        int t   = e >> 10;
        int rr  = (e >> 4) & 63;
        int seg = e & 15;
        const char* src = gb + ((size_t)t * KCB + (size_t)c * NC + rr) * 256 + seg * 16;
        uint32_t dst = dbase + (uint32_t)t * BMAT + (uint32_t)rr * ASTRIDE + seg * 16;
        cpasync16(dst, src);
    }
}

// ---------------- main kernel ----------------
__global__ __launch_bounds__(TH, 1)
void vq_kernel(const float* __restrict__ x, const float* __restrict__ embed,
               float* __restrict__ out, int nrows, int write_idx) {
    extern __shared__ __align__(16) char smm[];
    const uint32_t sb = smem_u32(smm);
    const int tid = threadIdx.x;
    const int l = tid & 31;
    const int w = tid >> 5;
    const int wm = w & 3;      // M-warp: rows wm*32
    const int wn = w >> 2;     // N-warp: cols wn*32 within 64-chunk
    const int rowBase = blockIdx.x * MT;

    float* s_en = reinterpret_cast<float*>(smm + EN_OFF);
    #pragma unroll
    for (int i = 0; i < 4; i++) s_en[tid + i * TH] = g_enorm[tid + i * TH];

    // prefetch B chunk 0
    load_b(sb, 0, 0, tid);
    cp_commit();

    // A: load x rows, 3-term bf16 split into smem
    {
        const float4* gx = reinterpret_cast<const float4*>(x + (long long)rowBase * DDIM);
        #pragma unroll
        for (int i = 0; i < 16; i++) {
            int fi = tid + i * TH;             // 0..4095
            int r = fi >> 5;
            int k = (fi & 31) * 4;
            float4 v = gx[fi];
            float vv[4] = {v.x, v.y, v.z, v.w};
            unsigned short hb[4], mb[4], lb[4];
            #pragma unroll
            for (int j = 0; j < 4; j++) {
                __nv_bfloat16 h = __float2bfloat16_rn(vv[j]);
                float rr = vv[j] - __bfloat162float(h);
                __nv_bfloat16 m = __float2bfloat16_rn(rr);
                rr -= __bfloat162float(m);
                __nv_bfloat16 lo = __float2bfloat16_rn(rr);
                hb[j] = bfbits(h); mb[j] = bfbits(m); lb[j] = bfbits(lo);
            }
            uint32_t off = (uint32_t)r * ASTRIDE + (uint32_t)k * 2;
            uint2 uh = { (uint32_t)hb[0] | ((uint32_t)hb[1] << 16),
                         (uint32_t)hb[2] | ((uint32_t)hb[3] << 16) };
            uint2 um = { (uint32_t)mb[0] | ((uint32_t)mb[1] << 16),
                         (uint32_t)mb[2] | ((uint32_t)mb[3] << 16) };
            uint2 ul = { (uint32_t)lb[0] | ((uint32_t)lb[1] << 16),
                         (uint32_t)lb[2] | ((uint32_t)lb[3] << 16) };
            *reinterpret_cast<uint2*>(smm + A_OFF + 0 * AMAT + off) = uh;
            *reinterpret_cast<uint2*>(smm + A_OFF + 1 * AMAT + off) = um;
            *reinterpret_cast<uint2*>(smm + A_OFF + 2 * AMAT + off) = ul;
        }
    }

    float best[2][2];
    int   bidx[2][2];
    #pragma unroll
    for (int a = 0; a < 2; a++)
        #pragma unroll
        for (int b = 0; b < 2; b++) { best[a][b] = -3.4e38f; bidx[a][b] = 0; }

    // ldmatrix lane address offsets (canonical sm_80 patterns)
    const uint32_t aLane = (uint32_t)((l & 15) * ASTRIDE + ((l >> 4) & 1) * 16);
    const uint32_t bLane = (uint32_t)((((l & 7) + ((l >> 4) << 3)) * ASTRIDE) + ((l >> 3) & 1) * 16);
    const uint32_t aBase = sb + A_OFF + (uint32_t)wm * 8704 + aLane;

    for (int c = 0; c < NCHUNK; c++) {
        if (c + 1 < NCHUNK) {
            load_b(sb, c + 1, (c + 1) & 1, tid);
            cp_commit();
            cp_wait1();
        } else {
            cp_wait0();
        }
        __syncthreads();

        float acc[2][4][4];
        #pragma unroll
        for (int mi = 0; mi < 2; mi++)
            #pragma unroll
            for (int ni = 0; ni < 4; ni++)
                #pragma unroll
                for (int k = 0; k < 4; k++) acc[mi][ni][k] = 0.f;

        const uint32_t bBase = sb + B_OFF + (uint32_t)(c & 1) * (3 * BMAT)
                             + (uint32_t)wn * 8704 + bLane;
        #pragma unroll
        for (int ks = 0; ks < 8; ks++) {
            uint32_t ak = aBase + (uint32_t)ks * 32;
            uint32_t bk = bBase + (uint32_t)ks * 32;
            uint32_t Ah[2][4], Am[2][4], Al[2][4];
            ldsm4(Ah[0], ak);              ldsm4(Ah[1], ak + 4352);
            ldsm4(Am[0], ak + AMAT);       ldsm4(Am[1], ak + AMAT + 4352);
            ldsm4(Al[0], ak + 2 * AMAT);   ldsm4(Al[1], ak + 2 * AMAT + 4352);
            uint32_t Bh[2][4], Bm[2][4], Bl[2][4];
            ldsm4(Bh[0], bk);              ldsm4(Bh[1], bk + 4352);
            ldsm4(Bm[0], bk + BMAT);       ldsm4(Bm[1], bk + BMAT + 4352);
            ldsm4(Bl[0], bk + 2 * BMAT);   ldsm4(Bl[1], bk + 2 * BMAT + 4352);
            #pragma unroll
            for (int mi = 0; mi < 2; mi++)
                #pragma unroll
                for (int np = 0; np < 2; np++)
                    #pragma unroll
                    for (int ah = 0; ah < 2; ah++) {
                        float* C = acc[mi][np * 2 + ah];
                        mma16816(C, Ah[mi], &Bh[np][2 * ah]);   // h*h
                        mma16816(C, Ah[mi], &Bm[np][2 * ah]);   // h*m
                        mma16816(C, Am[mi], &Bh[np][2 * ah]);   // m*h
                        mma16816(C, Ah[mi], &Bl[np][2 * ah]);   // h*l
                        mma16816(C, Al[mi], &Bh[np][2 * ah]);   // l*h
                        mma16816(C, Am[mi], &Bm[np][2 * ah]);   // m*m
                    }
        }

        // epilogue: score = 2*dot - ||e||^2, per-thread argmax update
        const int cb = c * NC;
        #pragma unroll
        for (int mi = 0; mi < 2; mi++)
            #pragma unroll
            for (int ni = 0; ni < 4; ni++) {
                int col0 = cb + wn * 32 + ni * 8 + (l & 3) * 2;
                float2 en = *reinterpret_cast<float2*>(&s_en[col0]);
                float s0 = fmaf(2.f, acc[mi][ni][0], -en.x);
                float s1 = fmaf(2.f, acc[mi][ni][1], -en.y);
                float s2 = fmaf(2.f, acc[mi][ni][2], -en.x);
                float s3 = fmaf(2.f, acc[mi][ni][3], -en.y);
                if (s0 > best[mi][0]) { best[mi][0] = s0; bidx[mi][0] = col0; }
                if (s1 > best[mi][0]) { best[mi][0] = s1; bidx[mi][0] = col0 + 1; }
                if (s2 > best[mi][1]) { best[mi][1] = s2; bidx[mi][1] = col0; }
                if (s3 > best[mi][1]) { best[mi][1] = s3; bidx[mi][1] = col0 + 1; }
            }
        __syncthreads();   // all reads of this B stage done before reuse
    }

    // ---- reduce: quad shfl, then cross-N-warp smem merge ----
    float* sval = reinterpret_cast<float*>(smm + RED_OFF);
    int*   sidx = reinterpret_cast<int*>(smm + RED_OFF + 1024);
    #pragma unroll
    for (int mi = 0; mi < 2; mi++)
        #pragma unroll
        for (int h = 0; h < 2; h++) {
            float v = best[mi][h];
            int   k = bidx[mi][h];
            #pragma unroll
            for (int off = 1; off < 4; off <<= 1) {
                float ov = __shfl_xor_sync(0xffffffffu, v, off);
                int   oi = __shfl_xor_sync(0xffffffffu, k, off);
                if (ov > v || (ov == v && oi < k)) { v = ov; k = oi; }
            }
            if ((l & 3) == 0) {
                int row = wm * 32 + mi * 16 + (l >> 2) + h * 8;
                sval[wn * 128 + row] = v;
                sidx[wn * 128 + row] = k;
            }
        }
    __syncthreads();

    int* sbi = reinterpret_cast<int*>(smm + RED_OFF);   // reuse sval region
    if (tid < 128) {
        float v0 = sval[tid], v1 = sval[128 + tid];
        int   k0 = sidx[tid], k1 = sidx[128 + tid];
        int k = (v1 > v0 || (v1 == v0 && k1 < k0)) ? k1 : k0;
        sbi[tid] = k;
        if (write_idx)
            out[(long long)nrows * DDIM + rowBase + tid] = (float)k;
    }
    __syncthreads();

    // ---- gather winning codewords (coalesced float4) ----
    {
        float4* go = reinterpret_cast<float4*>(out);
        const float4* ge = reinterpret_cast<const float4*>(embed);
        #pragma unroll
        for (int i = 0; i < 16; i++) {
            int idx = tid + i * TH;        // [128 rows][32 f4]
            int row = idx >> 5;
            int c4  = idx & 31;
            int k = sbi[row];
            go[((long long)(rowBase + row) << 5) + c4] = ge[(k << 5) + c4];
        }
    }
}

extern "C" void kernel_launch(void* const* d_in, const int* in_sizes, int n_in,
                              void* d_out, int out_size) {
    const float* x     = (const float*)d_in[0];
    const float* embed = (const float*)d_in[1];
    float* out = (float*)d_out;

    int nrows = in_sizes[0] / DDIM;  // 96000
    int write_idx = (out_size >= nrows * DDIM + nrows) ? 1 : 0;

    prep_split_kernel<<<(KCB * DDIM + 255) / 256, 256>>>(embed);
    enorm_kernel<<<(KCB + 255) / 256, 256>>>(embed);

    cudaFuncSetAttribute(vq_kernel,
                         cudaFuncAttributeMaxDynamicSharedMemorySize, SMEM_TOTAL);
    vq_kernel<<<nrows / MT, TH, SMEM_TOTAL>>>(x, embed, out, nrows, write_idx);
}

// round 8
// speedup vs baseline: 2.7222x; 1.6605x over previous
#include <cuda_runtime.h>
#include <cuda_fp16.h>
#include <cstdint>

#define DDIM 128
#define KCB  1024
#define MT   128          // rows per CTA
#define NC   64           // codes per chunk
#define NCHUNK 16
#define TH   256

#define ESCALE 32.0f      // embed pre-scale (power of 2; keeps l_e out of subnormal floor)
#define INV2ESCALE 0.0625f  // 2/32

#define ASTRIDE 272                   // bytes per smem row (136 fp16, LDSM conflict-free)
#define AMAT   (128 * ASTRIDE)        // 34816 B per A term matrix
#define BMAT   (64 * ASTRIDE)         // 17408 B per B term matrix
#define A_OFF  0                      // A: h,l consecutive (2*AMAT = 69632)
#define B_OFF  (2 * AMAT)             // 69632; single stage, 2 terms
#define EN_OFF (B_OFF + 2 * BMAT)     // 104448: 1024 floats
#define RED_OFF (EN_OFF + 4096)       // 108544: val f32[256] + idx i32[256]
#define SMEM_TOTAL (RED_OFF + 2048)   // 110592  -> 2 CTAs/SM

__device__ float g_enorm[KCB];
__device__ __align__(16) unsigned short g_fsplit[2][KCB][DDIM];  // fp16 bits of 32*embed: h,l

// ---------------- PTX helpers (baseline ISA only) ----------------
static __device__ __forceinline__ uint32_t smem_u32(const void* p) {
    uint32_t a;
    asm("{ .reg .u64 t; cvta.to.shared.u64 t, %1; cvt.u32.u64 %0, t; }"
        : "=r"(a) : "l"(p));
    return a;
}
static __device__ __forceinline__ void ldsm4(uint32_t* r, uint32_t a) {
    asm volatile("ldmatrix.sync.aligned.m8n8.x4.shared.b16 {%0,%1,%2,%3}, [%4];"
                 : "=r"(r[0]), "=r"(r[1]), "=r"(r[2]), "=r"(r[3]) : "r"(a));
}
static __device__ __forceinline__ void mma16816(float* c, const uint32_t* a,
                                                const uint32_t* b2) {
    asm volatile(
        "mma.sync.aligned.m16n8k16.row.col.f32.f16.f16.f32 "
        "{%0,%1,%2,%3}, {%4,%5,%6,%7}, {%8,%9}, {%0,%1,%2,%3};"
        : "+f"(c[0]), "+f"(c[1]), "+f"(c[2]), "+f"(c[3])
        : "r"(a[0]), "r"(a[1]), "r"(a[2]), "r"(a[3]), "r"(b2[0]), "r"(b2[1]));
}
static __device__ __forceinline__ void cpasync16(uint32_t dst, const void* src) {
    asm volatile("cp.async.cg.shared.global [%0], [%1], 16;" :: "r"(dst), "l"(src));
}
static __device__ __forceinline__ void cp_commit() {
    asm volatile("cp.async.commit_group;" ::: "memory");
}
static __device__ __forceinline__ void cp_wait0() {
    asm volatile("cp.async.wait_group 0;" ::: "memory");
}
static __device__ __forceinline__ unsigned short hbits(__half h) {
    return *reinterpret_cast<unsigned short*>(&h);
}

// ---------------- prep kernels ----------------
__global__ void prep_split_kernel(const float* __restrict__ embed) {
    int i = blockIdx.x * blockDim.x + threadIdx.x;
    if (i < KCB * DDIM) {
        float v = embed[i] * ESCALE;
        __half h = __float2half_rn(v);
        float r = v - __half2float(h);
        __half l = __float2half_rn(r);
        unsigned short* p = &g_fsplit[0][0][0];
        p[i] = hbits(h);
        p[KCB * DDIM + i] = hbits(l);
    }
}
__global__ void enorm_kernel(const float* __restrict__ embed) {
    int k = blockIdx.x * blockDim.x + threadIdx.x;
    if (k < KCB) {
        const float4* row = reinterpret_cast<const float4*>(embed + (long long)k * DDIM);
        float s = 0.f;
        #pragma unroll
        for (int i = 0; i < DDIM / 4; i++) {
            float4 v = row[i];
            s = fmaf(v.x, v.x, s); s = fmaf(v.y, v.y, s);
            s = fmaf(v.z, v.z, s); s = fmaf(v.w, v.w, s);
        }
        g_enorm[k] = s;
    }
}

// ---------------- B chunk loader (cp.async, 2 terms x 64 rows x 256B) ----------------
static __device__ __forceinline__ void load_b(uint32_t sb, int c, int tid) {
    uint32_t dbase = sb + B_OFF;
    const char* gb = reinterpret_cast<const char*>(&g_fsplit[0][0][0]);
    #pragma unroll
    for (int i = 0; i < 8; i++) {
        int e = tid + i * TH;         // 0..2047  (2 terms x 64 rows x 16 segs)
        int t   = e >> 10;
        int rr  = (e >> 4) & 63;
        int seg = e & 15;
        const char* src = gb + ((size_t)t * KCB + (size_t)c * NC + rr) * 256 + seg * 16;
        uint32_t dst = dbase + (uint32_t)t * BMAT + (uint32_t)rr * ASTRIDE + seg * 16;
        cpasync16(dst, src);
    }
}

// ---------------- main kernel ----------------
__global__ __launch_bounds__(TH, 2)
void vq_kernel(const float* __restrict__ x, const float* __restrict__ embed,
               float* __restrict__ out, int nrows, int write_idx) {
    extern __shared__ __align__(16) char smm[];
    const uint32_t sb = smem_u32(smm);
    const int tid = threadIdx.x;
    const int l = tid & 31;
    const int w = tid >> 5;
    const int wm = w & 3;      // M-warp: rows wm*32
    const int wn = w >> 2;     // N-warp: cols wn*32 within 64-chunk
    const int rowBase = blockIdx.x * MT;

    float* s_en = reinterpret_cast<float*>(smm + EN_OFF);
    #pragma unroll
    for (int i = 0; i < 4; i++) s_en[tid + i * TH] = g_enorm[tid + i * TH];

    // prefetch B chunk 0
    load_b(sb, 0, tid);
    cp_commit();

    // A: load x rows, 2-term fp16 split into smem (x unscaled)
    {
        const float4* gx = reinterpret_cast<const float4*>(x + (long long)rowBase * DDIM);
        #pragma unroll
        for (int i = 0; i < 16; i++) {
            int fi = tid + i * TH;             // 0..4095
            int r = fi >> 5;
            int k = (fi & 31) * 4;
            float4 v = gx[fi];
            float vv[4] = {v.x, v.y, v.z, v.w};
            unsigned short hb[4], lb[4];
            #pragma unroll
            for (int j = 0; j < 4; j++) {
                __half h = __float2half_rn(vv[j]);
                float rr = vv[j] - __half2float(h);
                __half lo = __float2half_rn(rr);
                hb[j] = hbits(h); lb[j] = hbits(lo);
            }
            uint32_t off = (uint32_t)r * ASTRIDE + (uint32_t)k * 2;
            uint2 uh = { (uint32_t)hb[0] | ((uint32_t)hb[1] << 16),
                         (uint32_t)hb[2] | ((uint32_t)hb[3] << 16) };
            uint2 ul = { (uint32_t)lb[0] | ((uint32_t)lb[1] << 16),
                         (uint32_t)lb[2] | ((uint32_t)lb[3] << 16) };
            *reinterpret_cast<uint2*>(smm + A_OFF + 0 * AMAT + off) = uh;
            *reinterpret_cast<uint2*>(smm + A_OFF + 1 * AMAT + off) = ul;
        }
    }

    float best[2][2];
    int   bidx[2][2];
    #pragma unroll
    for (int a = 0; a < 2; a++)
        #pragma unroll
        for (int b = 0; b < 2; b++) { best[a][b] = -3.4e38f; bidx[a][b] = 0; }

    // ldmatrix lane address offsets (validated in R7)
    const uint32_t aLane = (uint32_t)((l & 15) * ASTRIDE + ((l >> 4) & 1) * 16);
    const uint32_t bLane = (uint32_t)((((l & 7) + ((l >> 4) << 3)) * ASTRIDE) + ((l >> 3) & 1) * 16);
    const uint32_t aBase = sb + A_OFF + (uint32_t)wm * 8704 + aLane;
    const uint32_t bBase0 = sb + B_OFF + (uint32_t)wn * 8704 + bLane;

    for (int c = 0; c < NCHUNK; c++) {
        cp_wait0();
        __syncthreads();          // B(c) ready & A visible (first iter)

        float acc[2][4][4];
        #pragma unroll
        for (int mi = 0; mi < 2; mi++)
            #pragma unroll
            for (int ni = 0; ni < 4; ni++)
                #pragma unroll
                for (int k = 0; k < 4; k++) acc[mi][ni][k] = 0.f;

        #pragma unroll
        for (int ks = 0; ks < 8; ks++) {
            uint32_t ak = aBase + (uint32_t)ks * 32;
            uint32_t bk = bBase0 + (uint32_t)ks * 32;
            uint32_t Ah[2][4], Al[2][4];
            ldsm4(Ah[0], ak);            ldsm4(Ah[1], ak + 4352);
            ldsm4(Al[0], ak + AMAT);     ldsm4(Al[1], ak + AMAT + 4352);
            uint32_t Bh[2][4], Bl[2][4];
            ldsm4(Bh[0], bk);            ldsm4(Bh[1], bk + 4352);
            ldsm4(Bl[0], bk + BMAT);     ldsm4(Bl[1], bk + BMAT + 4352);
            #pragma unroll
            for (int mi = 0; mi < 2; mi++)
                #pragma unroll
                for (int np = 0; np < 2; np++)
                    #pragma unroll
                    for (int ah = 0; ah < 2; ah++) {
                        float* C = acc[mi][np * 2 + ah];
                        mma16816(C, Ah[mi], &Bh[np][2 * ah]);   // h*h
                        mma16816(C, Ah[mi], &Bl[np][2 * ah]);   // h*l
                        mma16816(C, Al[mi], &Bh[np][2 * ah]);   // l*h
                    }
        }

        // epilogue: score = 2*(dot/32) - ||e||^2, per-thread argmax
        const int cb = c * NC;
        #pragma unroll
        for (int mi = 0; mi < 2; mi++)
            #pragma unroll
            for (int ni = 0; ni < 4; ni++) {
                int col0 = cb + wn * 32 + ni * 8 + (l & 3) * 2;
                float2 en = *reinterpret_cast<float2*>(&s_en[col0]);
                float s0 = fmaf(INV2ESCALE, acc[mi][ni][0], -en.x);
                float s1 = fmaf(INV2ESCALE, acc[mi][ni][1], -en.y);
                float s2 = fmaf(INV2ESCALE, acc[mi][ni][2], -en.x);
                float s3 = fmaf(INV2ESCALE, acc[mi][ni][3], -en.y);
                if (s0 > best[mi][0]) { best[mi][0] = s0; bidx[mi][0] = col0; }
                if (s1 > best[mi][0]) { best[mi][0] = s1; bidx[mi][0] = col0 + 1; }
                if (s2 > best[mi][1]) { best[mi][1] = s2; bidx[mi][1] = col0; }
                if (s3 > best[mi][1]) { best[mi][1] = s3; bidx[mi][1] = col0 + 1; }
            }
        __syncthreads();          // all warps done reading B(c)

        if (c + 1 < NCHUNK) {
            load_b(sb, c + 1, tid);
            cp_commit();
        }
    }

    // ---- reduce: quad shfl, then cross-N-warp smem merge ----
    float* sval = reinterpret_cast<float*>(smm + RED_OFF);
    int*   sidx = reinterpret_cast<int*>(smm + RED_OFF + 1024);
    #pragma unroll
    for (int mi = 0; mi < 2; mi++)
        #pragma unroll
        for (int h = 0; h < 2; h++) {
            float v = best[mi][h];
            int   k = bidx[mi][h];
            #pragma unroll
            for (int off = 1; off < 4; off <<= 1) {
                float ov = __shfl_xor_sync(0xffffffffu, v, off);
                int   oi = __shfl_xor_sync(0xffffffffu, k, off);
                if (ov > v || (ov == v && oi < k)) { v = ov; k = oi; }
            }
            if ((l & 3) == 0) {
                int row = wm * 32 + mi * 16 + (l >> 2) + h * 8;
                sval[wn * 128 + row] = v;
                sidx[wn * 128 + row] = k;
            }
        }
    __syncthreads();

    int* sbi = reinterpret_cast<int*>(smm + RED_OFF);   // reuse sval region
    if (tid < 128) {
        float v0 = sval[tid], v1 = sval[128 + tid];
        int   k0 = sidx[tid], k1 = sidx[128 + tid];
        int k = (v1 > v0 || (v1 == v0 && k1 < k0)) ? k1 : k0;
        sbi[tid] = k;
        if (write_idx)
            out[(long long)nrows * DDIM + rowBase + tid] = (float)k;
    }
    __syncthreads();

    // ---- gather winning codewords (coalesced float4) ----
    {
        float4* go = reinterpret_cast<float4*>(out);
        const float4* ge = reinterpret_cast<const float4*>(embed);
        #pragma unroll
        for (int i = 0; i < 16; i++) {
            int idx = tid + i * TH;        // [128 rows][32 f4]
            int row = idx >> 5;
            int c4  = idx & 31;
            int k = sbi[row];
            go[((long long)(rowBase + row) << 5) + c4] = ge[(k << 5) + c4];
        }
    }
}

extern "C" void kernel_launch(void* const* d_in, const int* in_sizes, int n_in,
                              void* d_out, int out_size) {
    const float* x     = (const float*)d_in[0];
    const float* embed = (const float*)d_in[1];
    float* out = (float*)d_out;

    int nrows = in_sizes[0] / DDIM;  // 96000
    int write_idx = (out_size >= nrows * DDIM + nrows) ? 1 : 0;

    prep_split_kernel<<<(KCB * DDIM + 255) / 256, 256>>>(embed);
    enorm_kernel<<<(KCB + 255) / 256, 256>>>(embed);

    cudaFuncSetAttribute(vq_kernel,
                         cudaFuncAttributeMaxDynamicSharedMemorySize, SMEM_TOTAL);
    vq_kernel<<<nrows / MT, TH, SMEM_TOTAL>>>(x, embed, out, nrows, write_idx);
}

// round 9
// speedup vs baseline: 3.0859x; 1.1336x over previous
#include <cuda_runtime.h>
#include <cuda_fp16.h>
#include <cstdint>

#define DDIM 128
#define KCB  1024
#define MT   128          // rows per CTA
#define NC   64           // codes per chunk
#define NCHUNK 16
#define TH   256

#define ESCALE 32.0f        // embed pre-scale (power of 2; keeps l_e out of subnormal floor)
#define INV2ESCALE 0.0625f  // 2/32

#define ASTRIDE 272                   // bytes per smem row (136 fp16, LDSM conflict-free)
#define AMAT   (128 * ASTRIDE)        // 34816 B per A term matrix
#define BMAT   (64 * ASTRIDE)         // 17408 B per B term matrix
#define A_OFF  0                      // A: h,l consecutive (2*AMAT = 69632)
#define B_OFF  (2 * AMAT)             // 69632; single stage, 2 terms
#define EN_OFF (B_OFF + 2 * BMAT)     // 104448: 1024 floats
#define RED_OFF (EN_OFF + 4096)       // 108544: val f32[256] + idx i32[256]
#define SMEM_TOTAL (RED_OFF + 2048)   // 110592  -> 2 CTAs/SM

__device__ float g_enorm[KCB];
__device__ __align__(16) unsigned short g_fsplit[2][KCB][DDIM];  // fp16 bits of 32*embed: h,l

// ---------------- PTX helpers (baseline ISA only) ----------------
static __device__ __forceinline__ uint32_t smem_u32(const void* p) {
    uint32_t a;
    asm("{ .reg .u64 t; cvta.to.shared.u64 t, %1; cvt.u32.u64 %0, t; }"
        : "=r"(a) : "l"(p));
    return a;
}
static __device__ __forceinline__ void ldsm4(uint32_t* r, uint32_t a) {
    asm volatile("ldmatrix.sync.aligned.m8n8.x4.shared.b16 {%0,%1,%2,%3}, [%4];"
                 : "=r"(r[0]), "=r"(r[1]), "=r"(r[2]), "=r"(r[3]) : "r"(a));
}
static __device__ __forceinline__ void mma16816(float* c, const uint32_t* a,
                                                const uint32_t* b2) {
    asm volatile(
        "mma.sync.aligned.m16n8k16.row.col.f32.f16.f16.f32 "
        "{%0,%1,%2,%3}, {%4,%5,%6,%7}, {%8,%9}, {%0,%1,%2,%3};"
        : "+f"(c[0]), "+f"(c[1]), "+f"(c[2]), "+f"(c[3])
        : "r"(a[0]), "r"(a[1]), "r"(a[2]), "r"(a[3]), "r"(b2[0]), "r"(b2[1]));
}
static __device__ __forceinline__ void cpasync16(uint32_t dst, const void* src) {
    asm volatile("cp.async.cg.shared.global [%0], [%1], 16;" :: "r"(dst), "l"(src));
}
static __device__ __forceinline__ void cp_commit() {
    asm volatile("cp.async.commit_group;" ::: "memory");
}
static __device__ __forceinline__ void cp_wait0() {
    asm volatile("cp.async.wait_group 0;" ::: "memory");
}
static __device__ __forceinline__ unsigned short hbits(__half h) {
    return *reinterpret_cast<unsigned short*>(&h);
}

// ---------------- fused prep kernel: split + enorm ----------------
__global__ void prep_kernel(const float* __restrict__ embed) {
    int i = blockIdx.x * blockDim.x + threadIdx.x;
    if (i < KCB * DDIM) {
        float v = embed[i] * ESCALE;
        __half h = __float2half_rn(v);
        float r = v - __half2float(h);
        __half l = __float2half_rn(r);
        unsigned short* p = &g_fsplit[0][0][0];
        p[i] = hbits(h);
        p[KCB * DDIM + i] = hbits(l);
    }
    // first 4 blocks also compute ||e||^2 (one row per thread)
    int k = blockIdx.x * blockDim.x + threadIdx.x;
    if (blockIdx.x < 4) {
        int row = k;                   // 0..1023
        const float4* rp = reinterpret_cast<const float4*>(embed + (long long)row * DDIM);
        float s = 0.f;
        #pragma unroll
        for (int j = 0; j < DDIM / 4; j++) {
            float4 v = rp[j];
            s = fmaf(v.x, v.x, s); s = fmaf(v.y, v.y, s);
            s = fmaf(v.z, v.z, s); s = fmaf(v.w, v.w, s);
        }
        g_enorm[row] = s;
    }
}

// ---------------- B chunk loader (cp.async, 2 terms x 64 rows x 256B) ----------------
static __device__ __forceinline__ void load_b(uint32_t sb, int c, int tid) {
    uint32_t dbase = sb + B_OFF;
    const char* gb = reinterpret_cast<const char*>(&g_fsplit[0][0][0]);
    #pragma unroll
    for (int i = 0; i < 8; i++) {
        int e = tid + i * TH;         // 0..2047  (2 terms x 64 rows x 16 segs)
        int t   = e >> 10;
        int rr  = (e >> 4) & 63;
        int seg = e & 15;
        const char* src = gb + ((size_t)t * KCB + (size_t)c * NC + rr) * 256 + seg * 16;
        uint32_t dst = dbase + (uint32_t)t * BMAT + (uint32_t)rr * ASTRIDE + seg * 16;
        cpasync16(dst, src);
    }
}

// ---------------- main kernel ----------------
__global__ __launch_bounds__(TH, 2)
void vq_kernel(const float* __restrict__ x, const float* __restrict__ embed,
               float* __restrict__ out, int nrows, int write_idx) {
    extern __shared__ __align__(16) char smm[];
    const uint32_t sb = smem_u32(smm);
    const int tid = threadIdx.x;
    const int l = tid & 31;
    const int w = tid >> 5;
    const int wm = w & 3;      // M-warp: rows wm*32
    const int wn = w >> 2;     // N-warp: cols wn*32 within 64-chunk
    const int rowBase = blockIdx.x * MT;

    float* s_en = reinterpret_cast<float*>(smm + EN_OFF);
    #pragma unroll
    for (int i = 0; i < 4; i++) s_en[tid + i * TH] = g_enorm[tid + i * TH];

    // prefetch B chunk 0
    load_b(sb, 0, tid);
    cp_commit();

    // A: load x rows, 2-term fp16 split into smem (x unscaled)
    {
        const float4* gx = reinterpret_cast<const float4*>(x + (long long)rowBase * DDIM);
        #pragma unroll
        for (int i = 0; i < 16; i++) {
            int fi = tid + i * TH;             // 0..4095
            int r = fi >> 5;
            int k = (fi & 31) * 4;
            float4 v = gx[fi];
            float vv[4] = {v.x, v.y, v.z, v.w};
            unsigned short hb[4], lb[4];
            #pragma unroll
            for (int j = 0; j < 4; j++) {
                __half h = __float2half_rn(vv[j]);
                float rr = vv[j] - __half2float(h);
                __half lo = __float2half_rn(rr);
                hb[j] = hbits(h); lb[j] = hbits(lo);
            }
            uint32_t off = (uint32_t)r * ASTRIDE + (uint32_t)k * 2;
            uint2 uh = { (uint32_t)hb[0] | ((uint32_t)hb[1] << 16),
                         (uint32_t)hb[2] | ((uint32_t)hb[3] << 16) };
            uint2 ul = { (uint32_t)lb[0] | ((uint32_t)lb[1] << 16),
                         (uint32_t)lb[2] | ((uint32_t)lb[3] << 16) };
            *reinterpret_cast<uint2*>(smm + A_OFF + 0 * AMAT + off) = uh;
            *reinterpret_cast<uint2*>(smm + A_OFF + 1 * AMAT + off) = ul;
        }
    }

    float best[2][2];
    int   bidx[2][2];
    #pragma unroll
    for (int a = 0; a < 2; a++)
        #pragma unroll
        for (int b = 0; b < 2; b++) { best[a][b] = -3.4e38f; bidx[a][b] = 0; }

    // ldmatrix lane address offsets (validated in R7/R8)
    const uint32_t aLane = (uint32_t)((l & 15) * ASTRIDE + ((l >> 4) & 1) * 16);
    const uint32_t bLane = (uint32_t)((((l & 7) + ((l >> 4) << 3)) * ASTRIDE) + ((l >> 3) & 1) * 16);
    const uint32_t aBase = sb + A_OFF + (uint32_t)wm * 8704 + aLane;
    const uint32_t bBase0 = sb + B_OFF + (uint32_t)wn * 8704 + bLane;

    for (int c = 0; c < NCHUNK; c++) {
        cp_wait0();
        __syncthreads();          // B(c) ready in smem (and A visible on first iter)

        float acc[2][4][4];
        #pragma unroll
        for (int mi = 0; mi < 2; mi++)
            #pragma unroll
            for (int ni = 0; ni < 4; ni++)
                #pragma unroll
                for (int k = 0; k < 4; k++) acc[mi][ni][k] = 0.f;

        #pragma unroll
        for (int ks = 0; ks < 8; ks++) {
            uint32_t ak = aBase + (uint32_t)ks * 32;
            uint32_t bk = bBase0 + (uint32_t)ks * 32;
            uint32_t Ah[2][4], Al[2][4];
            ldsm4(Ah[0], ak);            ldsm4(Ah[1], ak + 4352);
            ldsm4(Al[0], ak + AMAT);     ldsm4(Al[1], ak + AMAT + 4352);
            uint32_t Bh[2][4], Bl[2][4];
            ldsm4(Bh[0], bk);            ldsm4(Bh[1], bk + 4352);
            ldsm4(Bl[0], bk + BMAT);     ldsm4(Bl[1], bk + BMAT + 4352);
            #pragma unroll
            for (int mi = 0; mi < 2; mi++)
                #pragma unroll
                for (int np = 0; np < 2; np++)
                    #pragma unroll
                    for (int ah = 0; ah < 2; ah++) {
                        float* C = acc[mi][np * 2 + ah];
                        mma16816(C, Ah[mi], &Bh[np][2 * ah]);   // h*h
                        mma16816(C, Ah[mi], &Bl[np][2 * ah]);   // h*l
                        mma16816(C, Al[mi], &Bh[np][2 * ah]);   // l*h
                    }
        }

        // all warps done READING B(c) -> barrier, then immediately launch
        // the next chunk's cp.async so its flight overlaps the epilogue below
        __syncthreads();
        if (c + 1 < NCHUNK) {
            load_b(sb, c + 1, tid);
            cp_commit();
        }

        // epilogue: score = 2*(dot/32) - ||e||^2, per-thread argmax
        // (registers + s_en only -- does not touch the B region)
        const int cb = c * NC;
        #pragma unroll
        for (int mi = 0; mi < 2; mi++)
            #pragma unroll
            for (int ni = 0; ni < 4; ni++) {
                int col0 = cb + wn * 32 + ni * 8 + (l & 3) * 2;
                float2 en = *reinterpret_cast<float2*>(&s_en[col0]);
                float s0 = fmaf(INV2ESCALE, acc[mi][ni][0], -en.x);
                float s1 = fmaf(INV2ESCALE, acc[mi][ni][1], -en.y);
                float s2 = fmaf(INV2ESCALE, acc[mi][ni][2], -en.x);
                float s3 = fmaf(INV2ESCALE, acc[mi][ni][3], -en.y);
                if (s0 > best[mi][0]) { best[mi][0] = s0; bidx[mi][0] = col0; }
                if (s1 > best[mi][0]) { best[mi][0] = s1; bidx[mi][0] = col0 + 1; }
                if (s2 > best[mi][1]) { best[mi][1] = s2; bidx[mi][1] = col0; }
                if (s3 > best[mi][1]) { best[mi][1] = s3; bidx[mi][1] = col0 + 1; }
            }
    }

    // ---- reduce: quad shfl, then cross-N-warp smem merge ----
    float* sval = reinterpret_cast<float*>(smm + RED_OFF);
    int*   sidx = reinterpret_cast<int*>(smm + RED_OFF + 1024);
    #pragma unroll
    for (int mi = 0; mi < 2; mi++)
        #pragma unroll
        for (int h = 0; h < 2; h++) {
            float v = best[mi][h];
            int   k = bidx[mi][h];
            #pragma unroll
            for (int off = 1; off < 4; off <<= 1) {
                float ov = __shfl_xor_sync(0xffffffffu, v, off);
                int   oi = __shfl_xor_sync(0xffffffffu, k, off);
                if (ov > v || (ov == v && oi < k)) { v = ov; k = oi; }
            }
            if ((l & 3) == 0) {
                int row = wm * 32 + mi * 16 + (l >> 2) + h * 8;
                sval[wn * 128 + row] = v;
                sidx[wn * 128 + row] = k;
            }
        }
    __syncthreads();

    int* sbi = reinterpret_cast<int*>(smm + RED_OFF);   // reuse sval region
    if (tid < 128) {
        float v0 = sval[tid], v1 = sval[128 + tid];
        int   k0 = sidx[tid], k1 = sidx[128 + tid];
        int k = (v1 > v0 || (v1 == v0 && k1 < k0)) ? k1 : k0;
        sbi[tid] = k;
        if (write_idx)
            out[(long long)nrows * DDIM + rowBase + tid] = (float)k;
    }
    __syncthreads();

    // ---- gather winning codewords (coalesced float4) ----
    {
        float4* go = reinterpret_cast<float4*>(out);
        const float4* ge = reinterpret_cast<const float4*>(embed);
        #pragma unroll
        for (int i = 0; i < 16; i++) {
            int idx = tid + i * TH;        // [128 rows][32 f4]
            int row = idx >> 5;
            int c4  = idx & 31;
            int k = sbi[row];
            go[((long long)(rowBase + row) << 5) + c4] = ge[(k << 5) + c4];
        }
    }
}

extern "C" void kernel_launch(void* const* d_in, const int* in_sizes, int n_in,
                              void* d_out, int out_size) {
    const float* x     = (const float*)d_in[0];
    const float* embed = (const float*)d_in[1];
    float* out = (float*)d_out;

    int nrows = in_sizes[0] / DDIM;  // 96000
    int write_idx = (out_size >= nrows * DDIM + nrows) ? 1 : 0;

    prep_kernel<<<(KCB * DDIM + 255) / 256, 256>>>(embed);

    cudaFuncSetAttribute(vq_kernel,
                         cudaFuncAttributeMaxDynamicSharedMemorySize, SMEM_TOTAL);
    vq_kernel<<<nrows / MT, TH, SMEM_TOTAL>>>(x, embed, out, nrows, write_idx);
}

// round 10
// speedup vs baseline: 3.1128x; 1.0087x over previous
#include <cuda_runtime.h>
#include <cuda_fp16.h>
#include <cstdint>

#define DDIM 128
#define KCB  1024
#define MT   128          // rows per CTA
#define NC   64           // codes per chunk
#define NCHUNK 16
#define TH   256

#define ESCALE 32.0f        // embed pre-scale (power of 2; keeps l_e out of subnormal floor)
#define INV2ESCALE 0.0625f  // 2/32

#define ASTRIDE 272                   // bytes per smem row (136 fp16, LDSM conflict-free)
#define AMAT   (128 * ASTRIDE)        // 34816 B per A term matrix
#define BMAT   (64 * ASTRIDE)         // 17408 B per B term matrix
#define A_OFF  0                      // A: h,l consecutive (2*AMAT = 69632)
#define B_OFF  (2 * AMAT)             // 69632; single stage, 2 terms
#define EN_OFF (B_OFF + 2 * BMAT)     // 104448: 1024 floats
#define RED_OFF (EN_OFF + 4096)       // 108544: val f32[256] + idx i32[256]
#define SMEM_TOTAL (RED_OFF + 2048)   // 110592  -> 2 CTAs/SM

__device__ float g_enorm[KCB];
__device__ __align__(16) unsigned short g_fsplit[2][KCB][DDIM];  // fp16 bits of 32*embed: h,l

// ---------------- PTX helpers (baseline ISA only) ----------------
static __device__ __forceinline__ uint32_t smem_u32(const void* p) {
    uint32_t a;
    asm("{ .reg .u64 t; cvta.to.shared.u64 t, %1; cvt.u32.u64 %0, t; }"
        : "=r"(a) : "l"(p));
    return a;
}
static __device__ __forceinline__ void ldsm4(uint32_t* r, uint32_t a) {
    asm volatile("ldmatrix.sync.aligned.m8n8.x4.shared.b16 {%0,%1,%2,%3}, [%4];"
                 : "=r"(r[0]), "=r"(r[1]), "=r"(r[2]), "=r"(r[3]) : "r"(a));
}
static __device__ __forceinline__ void mma16816(float* c, const uint32_t* a,
                                                const uint32_t* b2) {
    asm volatile(
        "mma.sync.aligned.m16n8k16.row.col.f32.f16.f16.f32 "
        "{%0,%1,%2,%3}, {%4,%5,%6,%7}, {%8,%9}, {%0,%1,%2,%3};"
        : "+f"(c[0]), "+f"(c[1]), "+f"(c[2]), "+f"(c[3])
        : "r"(a[0]), "r"(a[1]), "r"(a[2]), "r"(a[3]), "r"(b2[0]), "r"(b2[1]));
}
static __device__ __forceinline__ void cpasync16(uint32_t dst, const void* src) {
    asm volatile("cp.async.cg.shared.global [%0], [%1], 16;" :: "r"(dst), "l"(src));
}
static __device__ __forceinline__ void cp_commit() {
    asm volatile("cp.async.commit_group;" ::: "memory");
}
static __device__ __forceinline__ void cp_wait0() {
    asm volatile("cp.async.wait_group 0;" ::: "memory");
}
static __device__ __forceinline__ unsigned short hbits(__half h) {
    return *reinterpret_cast<unsigned short*>(&h);
}

// ---------------- fused prep kernel: split + enorm ----------------
__global__ void prep_kernel(const float* __restrict__ embed) {
    int i = blockIdx.x * blockDim.x + threadIdx.x;
    if (i < KCB * DDIM) {
        float v = embed[i] * ESCALE;
        __half h = __float2half_rn(v);
        float r = v - __half2float(h);
        __half l = __float2half_rn(r);
        unsigned short* p = &g_fsplit[0][0][0];
        p[i] = hbits(h);
        p[KCB * DDIM + i] = hbits(l);
    }
    // first 4 blocks also compute ||e||^2 (one row per thread)
    int k = blockIdx.x * blockDim.x + threadIdx.x;
    if (blockIdx.x < 4) {
        int row = k;                   // 0..1023
        const float4* rp = reinterpret_cast<const float4*>(embed + (long long)row * DDIM);
        float s = 0.f;
        #pragma unroll
        for (int j = 0; j < DDIM / 4; j++) {
            float4 v = rp[j];
            s = fmaf(v.x, v.x, s); s = fmaf(v.y, v.y, s);
            s = fmaf(v.z, v.z, s); s = fmaf(v.w, v.w, s);
        }
        g_enorm[row] = s;
    }
}

// ---------------- B chunk loader (cp.async, 2 terms x 64 rows x 256B) ----------------
static __device__ __forceinline__ void load_b(uint32_t sb, int c, int tid) {
    uint32_t dbase = sb + B_OFF;
    const char* gb = reinterpret_cast<const char*>(&g_fsplit[0][0][0]);
    #pragma unroll
    for (int i = 0; i < 8; i++) {
        int e = tid + i * TH;         // 0..2047  (2 terms x 64 rows x 16 segs)
        int t   = e >> 10;
        int rr  = (e >> 4) & 63;
        int seg = e & 15;
        const char* src = gb + ((size_t)t * KCB + (size_t)c * NC + rr) * 256 + seg * 16;
        uint32_t dst = dbase + (uint32_t)t * BMAT + (uint32_t)rr * ASTRIDE + seg * 16;
        cpasync16(dst, src);
    }
}

// ---------------- main kernel ----------------
__global__ __launch_bounds__(TH, 2)
void vq_kernel(const float* __restrict__ x, const float* __restrict__ embed,
               float* __restrict__ out, int nrows, int write_idx) {
    extern __shared__ __align__(16) char smm[];
    const uint32_t sb = smem_u32(smm);
    const int tid = threadIdx.x;
    const int l = tid & 31;
    const int w = tid >> 5;
    const int wm = w & 3;      // M-warp: rows wm*32
    const int wn = w >> 2;     // N-warp: cols wn*32 within 64-chunk
    const int rowBase = blockIdx.x * MT;

    float* s_en = reinterpret_cast<float*>(smm + EN_OFF);
    #pragma unroll
    for (int i = 0; i < 4; i++) s_en[tid + i * TH] = g_enorm[tid + i * TH];

    // prefetch B chunk 0
    load_b(sb, 0, tid);
    cp_commit();

    // A: load x rows, 2-term fp16 split into smem (x unscaled)
    {
        const float4* gx = reinterpret_cast<const float4*>(x + (long long)rowBase * DDIM);
        #pragma unroll
        for (int i = 0; i < 16; i++) {
            int fi = tid + i * TH;             // 0..4095
            int r = fi >> 5;
            int k = (fi & 31) * 4;
            float4 v = gx[fi];
            float vv[4] = {v.x, v.y, v.z, v.w};
            unsigned short hb[4], lb[4];
            #pragma unroll
            for (int j = 0; j < 4; j++) {
                __half h = __float2half_rn(vv[j]);
                float rr = vv[j] - __half2float(h);
                __half lo = __float2half_rn(rr);
                hb[j] = hbits(h); lb[j] = hbits(lo);
            }
            uint32_t off = (uint32_t)r * ASTRIDE + (uint32_t)k * 2;
            uint2 uh = { (uint32_t)hb[0] | ((uint32_t)hb[1] << 16),
                         (uint32_t)hb[2] | ((uint32_t)hb[3] << 16) };
            uint2 ul = { (uint32_t)lb[0] | ((uint32_t)lb[1] << 16),
                         (uint32_t)lb[2] | ((uint32_t)lb[3] << 16) };
            *reinterpret_cast<uint2*>(smm + A_OFF + 0 * AMAT + off) = uh;
            *reinterpret_cast<uint2*>(smm + A_OFF + 1 * AMAT + off) = ul;
        }
    }

    float best[2][2];
    int   bidx[2][2];
    #pragma unroll
    for (int a = 0; a < 2; a++)
        #pragma unroll
        for (int b = 0; b < 2; b++) { best[a][b] = -3.4e38f; bidx[a][b] = 0; }

    // ldmatrix lane address offsets (validated in R7/R8)
    const uint32_t aLane = (uint32_t)((l & 15) * ASTRIDE + ((l >> 4) & 1) * 16);
    const uint32_t bLane = (uint32_t)((((l & 7) + ((l >> 4) << 3)) * ASTRIDE) + ((l >> 3) & 1) * 16);
    const uint32_t aBase = sb + A_OFF + (uint32_t)wm * 8704 + aLane;
    const uint32_t bBase0 = sb + B_OFF + (uint32_t)wn * 8704 + bLane;

    for (int c = 0; c < NCHUNK; c++) {
        cp_wait0();
        __syncthreads();          // B(c) ready in smem (and A visible on first iter)

        float acc[2][4][4];
        #pragma unroll
        for (int mi = 0; mi < 2; mi++)
            #pragma unroll
            for (int ni = 0; ni < 4; ni++)
                #pragma unroll
                for (int k = 0; k < 4; k++) acc[mi][ni][k] = 0.f;

        #pragma unroll
        for (int ks = 0; ks < 8; ks++) {
            uint32_t ak = aBase + (uint32_t)ks * 32;
            uint32_t bk = bBase0 + (uint32_t)ks * 32;
            uint32_t Ah[2][4], Al[2][4];
            ldsm4(Ah[0], ak);            ldsm4(Ah[1], ak + 4352);
            ldsm4(Al[0], ak + AMAT);     ldsm4(Al[1], ak + AMAT + 4352);
            uint32_t Bh[2][4], Bl[2][4];
            ldsm4(Bh[0], bk);            ldsm4(Bh[1], bk + 4352);
            ldsm4(Bl[0], bk + BMAT);     ldsm4(Bl[1], bk + BMAT + 4352);
            #pragma unroll
            for (int mi = 0; mi < 2; mi++)
                #pragma unroll
                for (int np = 0; np < 2; np++)
                    #pragma unroll
                    for (int ah = 0; ah < 2; ah++) {
                        float* C = acc[mi][np * 2 + ah];
                        mma16816(C, Ah[mi], &Bh[np][2 * ah]);   // h*h
                        mma16816(C, Ah[mi], &Bl[np][2 * ah]);   // h*l
                        mma16816(C, Al[mi], &Bh[np][2 * ah]);   // l*h
                    }
        }

        // all warps done READING B(c) -> barrier, then immediately launch
        // the next chunk's cp.async so its flight overlaps the epilogue below
        __syncthreads();
        if (c + 1 < NCHUNK) {
            load_b(sb, c + 1, tid);
            cp_commit();
        }

        // epilogue: score = 2*(dot/32) - ||e||^2, per-thread argmax
        // (registers + s_en only -- does not touch the B region)
        const int cb = c * NC;
        #pragma unroll
        for (int mi = 0; mi < 2; mi++)
            #pragma unroll
            for (int ni = 0; ni < 4; ni++) {
                int col0 = cb + wn * 32 + ni * 8 + (l & 3) * 2;
                float2 en = *reinterpret_cast<float2*>(&s_en[col0]);
                float s0 = fmaf(INV2ESCALE, acc[mi][ni][0], -en.x);
                float s1 = fmaf(INV2ESCALE, acc[mi][ni][1], -en.y);
                float s2 = fmaf(INV2ESCALE, acc[mi][ni][2], -en.x);
                float s3 = fmaf(INV2ESCALE, acc[mi][ni][3], -en.y);
                if (s0 > best[mi][0]) { best[mi][0] = s0; bidx[mi][0] = col0; }
                if (s1 > best[mi][0]) { best[mi][0] = s1; bidx[mi][0] = col0 + 1; }
                if (s2 > best[mi][1]) { best[mi][1] = s2; bidx[mi][1] = col0; }
                if (s3 > best[mi][1]) { best[mi][1] = s3; bidx[mi][1] = col0 + 1; }
            }
    }

    // ---- reduce: quad shfl, then cross-N-warp smem merge ----
    float* sval = reinterpret_cast<float*>(smm + RED_OFF);
    int*   sidx = reinterpret_cast<int*>(smm + RED_OFF + 1024);
    #pragma unroll
    for (int mi = 0; mi < 2; mi++)
        #pragma unroll
        for (int h = 0; h < 2; h++) {
            float v = best[mi][h];
            int   k = bidx[mi][h];
            #pragma unroll
            for (int off = 1; off < 4; off <<= 1) {
                float ov = __shfl_xor_sync(0xffffffffu, v, off);
                int   oi = __shfl_xor_sync(0xffffffffu, k, off);
                if (ov > v || (ov == v && oi < k)) { v = ov; k = oi; }
            }
            if ((l & 3) == 0) {
                int row = wm * 32 + mi * 16 + (l >> 2) + h * 8;
                sval[wn * 128 + row] = v;
                sidx[wn * 128 + row] = k;
            }
        }
    __syncthreads();

    int* sbi = reinterpret_cast<int*>(smm + RED_OFF);   // reuse sval region
    if (tid < 128) {
        float v0 = sval[tid], v1 = sval[128 + tid];
        int   k0 = sidx[tid], k1 = sidx[128 + tid];
        int k = (v1 > v0 || (v1 == v0 && k1 < k0)) ? k1 : k0;
        sbi[tid] = k;
        if (write_idx)
            out[(long long)nrows * DDIM + rowBase + tid] = (float)k;
    }
    __syncthreads();

    // ---- gather winning codewords (coalesced float4) ----
    {
        float4* go = reinterpret_cast<float4*>(out);
        const float4* ge = reinterpret_cast<const float4*>(embed);
        #pragma unroll
        for (int i = 0; i < 16; i++) {
            int idx = tid + i * TH;        // [128 rows][32 f4]
            int row = idx >> 5;
            int c4  = idx & 31;
            int k = sbi[row];
            go[((long long)(rowBase + row) << 5) + c4] = ge[(k << 5) + c4];
        }
    }
}

extern "C" void kernel_launch(void* const* d_in, const int* in_sizes, int n_in,
                              void* d_out, int out_size) {
    const float* x     = (const float*)d_in[0];
    const float* embed = (const float*)d_in[1];
    float* out = (float*)d_out;

    int nrows = in_sizes[0] / DDIM;  // 96000
    int write_idx = (out_size >= nrows * DDIM + nrows) ? 1 : 0;

    prep_kernel<<<(KCB * DDIM + 255) / 256, 256>>>(embed);

    cudaFuncSetAttribute(vq_kernel,
                         cudaFuncAttributeMaxDynamicSharedMemorySize, SMEM_TOTAL);
    vq_kernel<<<nrows / MT, TH, SMEM_TOTAL>>>(x, embed, out, nrows, write_idx);
}